// round 13
// baseline (speedup 1.0000x reference)
#include <cuda_runtime.h>

// Problem shapes (fixed per reference setup_inputs)
#define BB  2
#define SS  2048
#define HH  4096
#define NHD 32
#define NSL 100
#define NP  128          // slots padded to 128
#define DD  64
#define BSR (BB*SS)      // 4096 rows

typedef unsigned long long ull;

// -------- scratch (no allocations allowed) --------
__device__ float g_gate[BSR];
__device__ float g_KW[HH*NP];       // (W_q^T keys^T)[h][n], pad n>=100 with 0
__device__ float g_logrelp[NP];     // log(rel+eps), pad = -1e30
__device__ float g_attn[BSR*NP];    // softmax(scores), un-gated
__device__ unsigned g_row_ticket;
__device__ unsigned g_out_ticket;

// -------- packed f32x2 helpers --------
__device__ __forceinline__ ull pk2(float lo, float hi){
    ull r; asm("mov.b64 %0, {%1, %2};" : "=l"(r) : "f"(lo), "f"(hi)); return r;
}
__device__ __forceinline__ void upk2(ull v, float& lo, float& hi){
    asm("mov.b64 {%0, %1}, %2;" : "=f"(lo), "=f"(hi) : "l"(v));
}
__device__ __forceinline__ void fma2(ull& d, ull a, ull b){
    asm("fma.rn.f32x2 %0, %1, %2, %0;" : "+l"(d) : "l"(a), "l"(b));
}
union F4U { float4 f; ull u[2]; };

// ============================================================
// reset: tickets only (also shifts the ncu -s window)
// ============================================================
__global__ void reset_kernel()
{
    if (threadIdx.x == 0) { g_row_ticket = 0u; g_out_ticket = 0u; }
}

// ============================================================
// prep_kw: KW[h][n] = sum_d Wq[d][h]*keys[n][d]
// grid (16, 8): block y owns n in [16y, 16y+16) -> 128 CTAs
// ============================================================
__global__ __launch_bounds__(256)
void prep_kw(const float* __restrict__ Wq,
             const float* __restrict__ keys,
             const float* __restrict__ rel)
{
    __shared__ float sk[16*DD];
    int t = threadIdx.x;
    int n0 = blockIdx.y * 16;
    for (int i = t; i < 16*DD; i += 256) {
        int n = i >> 6, d = i & 63;
        sk[i] = ((n0 + n) < NSL) ? keys[(n0+n)*DD + d] : 0.f;
    }
    __syncthreads();

    int h = blockIdx.x*256 + t;
    float wv[DD];
    #pragma unroll
    for (int d = 0; d < DD; ++d) wv[d] = Wq[(size_t)d*HH + h];

    #pragma unroll 4
    for (int n = 0; n < 16; ++n) {
        float acc = 0.f;
        const float* kn = sk + n*DD;
        #pragma unroll
        for (int d = 0; d < DD; ++d) acc += wv[d]*kn[d];
        g_KW[(size_t)h*NP + n0 + n] = acc;
    }
    if (blockIdx.x == 0 && blockIdx.y == 0 && t < NP)
        g_logrelp[t] = (t < NSL) ? __logf(rel[t] + 1e-10f) : -1e30f;
}

// ============================================================
// mega: grid = 444 (3 CTAs/SM, 48KB smem each = 144KB/SM).
//   blocks [0,296)    : entropy from t=0 (2 per SM -> 2x in-flight)
//   blocks [296,424)  : one scores tile (3rd slot), then entropy
//   blocks [424,444)  : entropy
// ============================================================
#define NENT2  296
#define NSCORE 128
#define NGRID (NENT2 + NSCORE + 20)   // 444

#define SKC 64
#define NCH (HH/SKC)     // 64 chunks
#define SCORES_SMEM (32*SKC*2 + SKC*NP)   // floats: 12288 -> 49152B

__device__ __forceinline__ void entropy_loop(const float* __restrict__ paw,
                                             float w1, float bb,
                                             unsigned* s_work, float* red)
{
    int t = threadIdx.x;
    for (;;) {
        __syncthreads();
        if (t == 0) *s_work = atomicAdd(&g_row_ticket, 1u);
        __syncthreads();
        unsigned row = *s_work;
        if (row >= BSR) break;

        size_t b = (size_t)(row >> 11);
        size_t s = (size_t)(row & 2047);
        const float* base = paw + ((b*NHD)*SS + s) * (size_t)SS;

        float4 a0 = make_float4(0.f,0.f,0.f,0.f);
        float4 a1 = make_float4(0.f,0.f,0.f,0.f);
        // unroll 4 (not 8): keeps regs ~50 so launch_bounds(256,3)
        // compiles spill-free; warp count now supplies the MLP.
        for (int h0 = 0; h0 < NHD; h0 += 4) {
            float4 x0[4], x1[4];
            #pragma unroll
            for (int u = 0; u < 4; ++u) {
                const float4* p = (const float4*)(base + (size_t)(h0+u)*SS*SS);
                x0[u] = p[t];
                x1[u] = p[t + 256];
            }
            #pragma unroll
            for (int u = 0; u < 4; ++u) {
                a0.x += x0[u].x; a0.y += x0[u].y; a0.z += x0[u].z; a0.w += x0[u].w;
                a1.x += x1[u].x; a1.y += x1[u].y; a1.z += x1[u].z; a1.w += x1[u].w;
            }
        }
        const float inv = 1.0f / 32.0f;
        float v[8] = {a0.x,a0.y,a0.z,a0.w,a1.x,a1.y,a1.z,a1.w};
        float loc = 0.f;
        #pragma unroll
        for (int i = 0; i < 8; ++i) {
            float a = v[i] * inv;
            loc += a * __logf(a + 1e-10f);
        }
        #pragma unroll
        for (int o = 16; o; o >>= 1) loc += __shfl_xor_sync(0xffffffffu, loc, o);
        if ((t & 31) == 0) red[t >> 5] = loc;
        __syncthreads();
        if (t == 0) {
            float tot = 0.f;
            #pragma unroll
            for (int i = 0; i < 8; ++i) tot += red[i];
            float e = -tot;
            float g = 1.0f / (1.0f + __expf(-(w1*e + bb)));
            if (e < 0.5f)       g = 0.f;
            else if (e > 2.0f)  g = fminf(g, 0.8f);
            g_gate[row] = g;
        }
    }
}

__global__ __launch_bounds__(256, 3)
void mega_kernel(const float* __restrict__ hidden,
                 const float* __restrict__ paw,
                 const float* __restrict__ w1p,
                 const float* __restrict__ bp)
{
    extern __shared__ float smraw[];
    __shared__ float red[8];
    __shared__ unsigned s_work;
    int t = threadIdx.x;
    int bid = blockIdx.x;

    if (bid >= NENT2 && bid < NENT2 + NSCORE) {
        // =================== one scores tile ===================
        float2* sh = (float2*)smraw;             // [32][SKC] dup pairs, 16KB
        float*  sw = smraw + 32*SKC*2;           // [SKC][NP], 32KB
        int w = t>>5, lane = t&31;
        int row0 = (bid - NENT2)*32;

        // register prefetch for hidden only (KW is L2-resident;
        // dropping its prefetch keeps regs under the 85 cap)
        float4 ph[2];
        #pragma unroll
        for (int i = 0; i < 2; ++i) {
            int idx = t + i*256, rr = idx>>4, c4 = idx&15;
            ph[i] = *(const float4*)(hidden + (size_t)(row0+rr)*HH + (c4<<2));
        }

        ull a[4][2] = {{0,0},{0,0},{0,0},{0,0}};

        for (int c = 0; c < NCH; ++c) {
            int k0 = c*SKC;
            __syncthreads();
            #pragma unroll
            for (int i = 0; i < 2; ++i) {
                int idx = t + i*256, rr = idx>>4, c4 = idx&15;
                float2* d = &sh[rr*SKC + (c4<<2)];
                d[0] = make_float2(ph[i].x, ph[i].x);
                d[1] = make_float2(ph[i].y, ph[i].y);
                d[2] = make_float2(ph[i].z, ph[i].z);
                d[3] = make_float2(ph[i].w, ph[i].w);
            }
            // KW chunk: direct L2 -> smem
            #pragma unroll
            for (int i = 0; i < 8; ++i) {
                int idx = t + i*256, kk = idx>>5, c4 = idx&31;
                *(float4*)(sw + kk*NP + (c4<<2)) =
                    *(const float4*)(g_KW + (size_t)(k0+kk)*NP + (c4<<2));
            }
            __syncthreads();

            if (c + 1 < NCH) {
                int k1 = k0 + SKC;
                #pragma unroll
                for (int i = 0; i < 2; ++i) {
                    int idx = t + i*256, rr = idx>>4, c4 = idx&15;
                    ph[i] = *(const float4*)(hidden + (size_t)(row0+rr)*HH + k1 + (c4<<2));
                }
            }

            const ull* h0 = (const ull*)&sh[(w*4+0)*SKC];
            const ull* h1 = (const ull*)&sh[(w*4+1)*SKC];
            const ull* h2 = (const ull*)&sh[(w*4+2)*SKC];
            const ull* h3 = (const ull*)&sh[(w*4+3)*SKC];
            #pragma unroll 8
            for (int k = 0; k < SKC; ++k) {
                F4U kw; kw.f = *(const float4*)(sw + k*NP + (lane<<2));
                ull hh0 = h0[k], hh1 = h1[k], hh2 = h2[k], hh3 = h3[k];
                fma2(a[0][0], kw.u[0], hh0); fma2(a[0][1], kw.u[1], hh0);
                fma2(a[1][0], kw.u[0], hh1); fma2(a[1][1], kw.u[1], hh1);
                fma2(a[2][0], kw.u[0], hh2); fma2(a[2][1], kw.u[1], hh2);
                fma2(a[3][0], kw.u[0], hh3); fma2(a[3][1], kw.u[1], hh3);
            }
        }

        // softmax per row (pad n>=100 has logrel=-1e30 -> exp=0)
        float4 lr = *(const float4*)(g_logrelp + (lane<<2));
        #pragma unroll
        for (int j = 0; j < 4; ++j) {
            int row = row0 + w*4 + j;
            float s0,s1,s2,s3;
            upk2(a[j][0], s0, s1); upk2(a[j][1], s2, s3);
            s0 = 0.125f*s0 + lr.x; s1 = 0.125f*s1 + lr.y;
            s2 = 0.125f*s2 + lr.z; s3 = 0.125f*s3 + lr.w;
            float m = fmaxf(fmaxf(s0,s1), fmaxf(s2,s3));
            #pragma unroll
            for (int o = 16; o; o >>= 1) m = fmaxf(m, __shfl_xor_sync(0xffffffffu, m, o));
            float e0 = __expf(s0-m), e1 = __expf(s1-m);
            float e2 = __expf(s2-m), e3 = __expf(s3-m);
            float sum = e0+e1+e2+e3;
            #pragma unroll
            for (int o = 16; o; o >>= 1) sum += __shfl_xor_sync(0xffffffffu, sum, o);
            float invs = 1.0f / sum;
            float4 o4 = make_float4(e0*invs, e1*invs, e2*invs, e3*invs);
            *(float4*)(g_attn + (size_t)row*NP + (lane<<2)) = o4;
        }
    }

    // =================== entropy (all CTAs) ===================
    entropy_loop(paw, w1p[0], bp[0], &s_work, red);
}

// ============================================================
// output: out = primary + gate[row]*(attn @ vals)
// PERSISTENT: grid 296 x 512 thr, ticket loop over 1024 tiles
// (tile = 32 rows x 512 cols). Proven R6/R12 inner structure.
// ============================================================
#define NOTILE (BSR/32 * 8)   // 1024 tiles
#define NOGRID 296

__global__ __launch_bounds__(512, 2)
void output_kernel(const float* __restrict__ primary,
                   const float* __restrict__ vals,
                   float* __restrict__ out)
{
    __shared__ ull attn2[NSL*16];   // [n][row-pair], 12.8KB
    __shared__ float sg[32];
    __shared__ unsigned s_tile;
    int t = threadIdx.x;

    for (;;) {
        __syncthreads();             // previous tile's attn2 reads done
        if (t == 0) s_tile = atomicAdd(&g_out_ticket, 1u);
        __syncthreads();
        unsigned tile = s_tile;
        if (tile >= NOTILE) break;

        int row0 = (int)(tile >> 3) * 32;
        int c    = (int)(tile & 7) * 512 + t;

        if (t < 32) sg[t] = g_gate[row0 + t];
        __syncthreads();
        for (int idx = t; idx < NSL*16; idx += 512) {
            int n = idx >> 4, rp = idx & 15;
            float a0 = g_attn[(size_t)(row0 + 2*rp  )*NP + n];
            float a1 = g_attn[(size_t)(row0 + 2*rp+1)*NP + n];
            attn2[n*16 + rp] = pk2(a0*sg[2*rp], a1*sg[2*rp+1]);
        }
        __syncthreads();

        ull acc[16];
        #pragma unroll
        for (int rp = 0; rp < 16; ++rp) {
            size_t rb = (size_t)(row0 + rp*2) * HH;
            acc[rp] = pk2(primary[rb + c], primary[rb + HH + c]);
        }

        // 4-deep prefetch ring on vals (L2-resident)
        float vr[4];
        #pragma unroll
        for (int i = 0; i < 4; ++i) vr[i] = vals[(size_t)i*HH + c];

        for (int n = 0; n < NSL; ++n) {
            int np = (n + 4 < NSL) ? n + 4 : NSL-1;
            float nv = vals[(size_t)np*HH + c];
            int sl = n & 3;
            ull vv = pk2(vr[sl], vr[sl]);
            const float4* arow = (const float4*)(attn2 + n*16);
            #pragma unroll
            for (int j = 0; j < 8; ++j) {
                F4U u; u.f = arow[j];        // broadcast LDS.128
                fma2(acc[2*j],   u.u[0], vv);
                fma2(acc[2*j+1], u.u[1], vv);
            }
            vr[sl] = nv;
        }

        #pragma unroll
        for (int rp = 0; rp < 16; ++rp) {
            float x, y;
            size_t rb = (size_t)(row0 + rp*2) * HH;
            upk2(acc[rp], x, y);
            out[rb + c] = x;
            out[rb + HH + c] = y;
        }
    }
}

// ============================================================
extern "C" void kernel_launch(void* const* d_in, const int* in_sizes, int n_in,
                              void* d_out, int out_size)
{
    const float* hidden  = (const float*)d_in[0];  // [B,S,H]
    const float* primary = (const float*)d_in[1];  // [B,S,H]
    const float* paw     = (const float*)d_in[2];  // [B,NH,S,S]
    const float* rel     = (const float*)d_in[3];  // [NS]
    const float* Wq      = (const float*)d_in[4];  // [D,H]
    const float* keys    = (const float*)d_in[5];  // [NS,D]
    const float* vals    = (const float*)d_in[6];  // [NS,H]
    const float* gw1     = (const float*)d_in[7];  // scalar
    const float* gb      = (const float*)d_in[8];  // scalar
    float* out = (float*)d_out;

    cudaFuncSetAttribute(mega_kernel,
                         cudaFuncAttributeMaxDynamicSharedMemorySize,
                         SCORES_SMEM * (int)sizeof(float));

    reset_kernel<<<1, 32>>>();
    prep_kw<<<dim3(HH/256, 8), 256>>>(Wq, keys, rel);
    mega_kernel<<<NGRID, 256, SCORES_SMEM * sizeof(float)>>>(hidden, paw, gw1, gb);
    output_kernel<<<NOGRID, 512>>>(primary, vals, out);
}

// round 14
// speedup vs baseline: 1.2144x; 1.2144x over previous
#include <cuda_runtime.h>

// Problem shapes (fixed per reference setup_inputs)
#define BB  2
#define SS  2048
#define HH  4096
#define NHD 32
#define NSL 100
#define NP  128          // slots padded to 128
#define DD  64
#define BSR (BB*SS)      // 4096 rows

typedef unsigned long long ull;

// -------- scratch (no allocations allowed) --------
__device__ float g_gate[BSR];
__device__ float g_KW[HH*NP];       // (W_q^T keys^T)[h][n], pad n>=100 with 0
__device__ float g_logrelp[NP];     // log(rel+eps), pad = -1e30
__device__ float g_attn[BSR*NP];    // softmax(scores), un-gated
__device__ unsigned g_row_ticket;
__device__ unsigned g_out_ticket;

// -------- packed f32x2 helpers --------
__device__ __forceinline__ ull pk2(float lo, float hi){
    ull r; asm("mov.b64 %0, {%1, %2};" : "=l"(r) : "f"(lo), "f"(hi)); return r;
}
__device__ __forceinline__ void upk2(ull v, float& lo, float& hi){
    asm("mov.b64 {%0, %1}, %2;" : "=f"(lo), "=f"(hi) : "l"(v));
}
__device__ __forceinline__ void fma2(ull& d, ull a, ull b){
    asm("fma.rn.f32x2 %0, %1, %2, %0;" : "+l"(d) : "l"(a), "l"(b));
}
union F4U { float4 f; ull u[2]; };

// ============================================================
// reset: tickets only (also shifts the ncu -s window)
// ============================================================
__global__ void reset_kernel()
{
    if (threadIdx.x == 0) { g_row_ticket = 0u; g_out_ticket = 0u; }
}

// ============================================================
// prep_kw: KW[h][n] = sum_d Wq[d][h]*keys[n][d]
// grid (16, 8): block y owns n in [16y, 16y+16) -> 128 CTAs
// ============================================================
__global__ __launch_bounds__(256)
void prep_kw(const float* __restrict__ Wq,
             const float* __restrict__ keys,
             const float* __restrict__ rel)
{
    __shared__ float sk[16*DD];
    int t = threadIdx.x;
    int n0 = blockIdx.y * 16;
    for (int i = t; i < 16*DD; i += 256) {
        int n = i >> 6, d = i & 63;
        sk[i] = ((n0 + n) < NSL) ? keys[(n0+n)*DD + d] : 0.f;
    }
    __syncthreads();

    int h = blockIdx.x*256 + t;
    float wv[DD];
    #pragma unroll
    for (int d = 0; d < DD; ++d) wv[d] = Wq[(size_t)d*HH + h];

    #pragma unroll 4
    for (int n = 0; n < 16; ++n) {
        float acc = 0.f;
        const float* kn = sk + n*DD;
        #pragma unroll
        for (int d = 0; d < DD; ++d) acc += wv[d]*kn[d];
        g_KW[(size_t)h*NP + n0 + n] = acc;
    }
    if (blockIdx.x == 0 && blockIdx.y == 0 && t < NP)
        g_logrelp[t] = (t < NSL) ? __logf(rel[t] + 1e-10f) : -1e30f;
}

// ============================================================
// mega: grid = 296 (2 CTAs/SM).  (exact R12/R6 structure)
//   blocks [0,148)    : entropy ticket loop from t=0
//   blocks [148,276)  : one scores tile, then join entropy
//   blocks [276,296)  : entropy
// ============================================================
#define NENT  148
#define NSCORE 128
#define NGRID (NENT + NSCORE + 20)   // 296

#define SKC 64
#define NCH (HH/SKC)     // 64 chunks
#define SCORES_SMEM (32*SKC*2 + SKC*NP)   // floats: 12288 -> 49152B

__device__ __forceinline__ void entropy_loop(const float* __restrict__ paw,
                                             float w1, float bb,
                                             unsigned* s_work, float* red)
{
    int t = threadIdx.x;
    for (;;) {
        __syncthreads();
        if (t == 0) *s_work = atomicAdd(&g_row_ticket, 1u);
        __syncthreads();
        unsigned row = *s_work;
        if (row >= BSR) break;

        size_t b = (size_t)(row >> 11);
        size_t s = (size_t)(row & 2047);
        const float* base = paw + ((b*NHD)*SS + s) * (size_t)SS;

        float4 a0 = make_float4(0.f,0.f,0.f,0.f);
        float4 a1 = make_float4(0.f,0.f,0.f,0.f);
        for (int h0 = 0; h0 < NHD; h0 += 8) {
            float4 x0[8], x1[8];
            #pragma unroll
            for (int u = 0; u < 8; ++u) {
                const float4* p = (const float4*)(base + (size_t)(h0+u)*SS*SS);
                x0[u] = p[t];
                x1[u] = p[t + 256];
            }
            #pragma unroll
            for (int u = 0; u < 8; ++u) {
                a0.x += x0[u].x; a0.y += x0[u].y; a0.z += x0[u].z; a0.w += x0[u].w;
                a1.x += x1[u].x; a1.y += x1[u].y; a1.z += x1[u].z; a1.w += x1[u].w;
            }
        }
        const float inv = 1.0f / 32.0f;
        float v[8] = {a0.x,a0.y,a0.z,a0.w,a1.x,a1.y,a1.z,a1.w};
        float loc = 0.f;
        #pragma unroll
        for (int i = 0; i < 8; ++i) {
            float a = v[i] * inv;
            loc += a * __logf(a + 1e-10f);
        }
        #pragma unroll
        for (int o = 16; o; o >>= 1) loc += __shfl_xor_sync(0xffffffffu, loc, o);
        if ((t & 31) == 0) red[t >> 5] = loc;
        __syncthreads();
        if (t == 0) {
            float tot = 0.f;
            #pragma unroll
            for (int i = 0; i < 8; ++i) tot += red[i];
            float e = -tot;
            float g = 1.0f / (1.0f + __expf(-(w1*e + bb)));
            if (e < 0.5f)       g = 0.f;
            else if (e > 2.0f)  g = fminf(g, 0.8f);
            g_gate[row] = g;
        }
    }
}

__global__ __launch_bounds__(256, 2)
void mega_kernel(const float* __restrict__ hidden,
                 const float* __restrict__ paw,
                 const float* __restrict__ w1p,
                 const float* __restrict__ bp)
{
    extern __shared__ float smraw[];
    __shared__ float red[8];
    __shared__ unsigned s_work;
    int t = threadIdx.x;
    int bid = blockIdx.x;

    if (bid >= NENT && bid < NENT + NSCORE) {
        // =================== one scores tile ===================
        float2* sh = (float2*)smraw;             // [32][SKC] dup pairs, 16KB
        float*  sw = smraw + 32*SKC*2;           // [SKC][NP], 32KB
        int w = t>>5, lane = t&31;
        int row0 = (bid - NENT)*32;

        float4 ph[2], pw[8];
        #pragma unroll
        for (int i = 0; i < 2; ++i) {
            int idx = t + i*256, rr = idx>>4, c4 = idx&15;
            ph[i] = *(const float4*)(hidden + (size_t)(row0+rr)*HH + (c4<<2));
        }
        #pragma unroll
        for (int i = 0; i < 8; ++i) {
            int idx = t + i*256, kk = idx>>5, c4 = idx&31;
            pw[i] = *(const float4*)(g_KW + (size_t)kk*NP + (c4<<2));
        }

        ull a[4][2] = {{0,0},{0,0},{0,0},{0,0}};

        for (int c = 0; c < NCH; ++c) {
            __syncthreads();
            #pragma unroll
            for (int i = 0; i < 2; ++i) {
                int idx = t + i*256, rr = idx>>4, c4 = idx&15;
                float2* d = &sh[rr*SKC + (c4<<2)];
                d[0] = make_float2(ph[i].x, ph[i].x);
                d[1] = make_float2(ph[i].y, ph[i].y);
                d[2] = make_float2(ph[i].z, ph[i].z);
                d[3] = make_float2(ph[i].w, ph[i].w);
            }
            #pragma unroll
            for (int i = 0; i < 8; ++i) {
                int idx = t + i*256, kk = idx>>5, c4 = idx&31;
                *(float4*)(sw + kk*NP + (c4<<2)) = pw[i];
            }
            __syncthreads();

            if (c + 1 < NCH) {
                int k0 = (c+1)*SKC;
                #pragma unroll
                for (int i = 0; i < 2; ++i) {
                    int idx = t + i*256, rr = idx>>4, c4 = idx&15;
                    ph[i] = *(const float4*)(hidden + (size_t)(row0+rr)*HH + k0 + (c4<<2));
                }
                #pragma unroll
                for (int i = 0; i < 8; ++i) {
                    int idx = t + i*256, kk = idx>>5, c4 = idx&31;
                    pw[i] = *(const float4*)(g_KW + (size_t)(k0+kk)*NP + (c4<<2));
                }
            }

            const ull* h0 = (const ull*)&sh[(w*4+0)*SKC];
            const ull* h1 = (const ull*)&sh[(w*4+1)*SKC];
            const ull* h2 = (const ull*)&sh[(w*4+2)*SKC];
            const ull* h3 = (const ull*)&sh[(w*4+3)*SKC];
            #pragma unroll 8
            for (int k = 0; k < SKC; ++k) {
                F4U kw; kw.f = *(const float4*)(sw + k*NP + (lane<<2));
                ull hh0 = h0[k], hh1 = h1[k], hh2 = h2[k], hh3 = h3[k];
                fma2(a[0][0], kw.u[0], hh0); fma2(a[0][1], kw.u[1], hh0);
                fma2(a[1][0], kw.u[0], hh1); fma2(a[1][1], kw.u[1], hh1);
                fma2(a[2][0], kw.u[0], hh2); fma2(a[2][1], kw.u[1], hh2);
                fma2(a[3][0], kw.u[0], hh3); fma2(a[3][1], kw.u[1], hh3);
            }
        }

        // softmax per row (pad n>=100 has logrel=-1e30 -> exp=0)
        float4 lr = *(const float4*)(g_logrelp + (lane<<2));
        #pragma unroll
        for (int j = 0; j < 4; ++j) {
            int row = row0 + w*4 + j;
            float s0,s1,s2,s3;
            upk2(a[j][0], s0, s1); upk2(a[j][1], s2, s3);
            s0 = 0.125f*s0 + lr.x; s1 = 0.125f*s1 + lr.y;
            s2 = 0.125f*s2 + lr.z; s3 = 0.125f*s3 + lr.w;
            float m = fmaxf(fmaxf(s0,s1), fmaxf(s2,s3));
            #pragma unroll
            for (int o = 16; o; o >>= 1) m = fmaxf(m, __shfl_xor_sync(0xffffffffu, m, o));
            float e0 = __expf(s0-m), e1 = __expf(s1-m);
            float e2 = __expf(s2-m), e3 = __expf(s3-m);
            float sum = e0+e1+e2+e3;
            #pragma unroll
            for (int o = 16; o; o >>= 1) sum += __shfl_xor_sync(0xffffffffu, sum, o);
            float invs = 1.0f / sum;
            float4 o4 = make_float4(e0*invs, e1*invs, e2*invs, e3*invs);
            *(float4*)(g_attn + (size_t)row*NP + (lane<<2)) = o4;
        }
    }

    // =================== entropy (all CTAs) ===================
    entropy_loop(paw, w1p[0], bp[0], &s_work, red);
}

// ============================================================
// output: out = primary + gate[row]*(attn @ vals)
// PERSISTENT: grid 296 x 512 thr, ticket loop over 1024 tiles.
// R12 structure + n-loop UNROLL 4 so the vals ring index (n&3)
// is compile-time constant -> vr[] stays in registers (the
// dynamic index was forcing local-memory LDL/STL through L1).
// ============================================================
#define NOTILE (BSR/32 * 8)   // 1024 tiles
#define NOGRID 296

__global__ __launch_bounds__(512, 2)
void output_kernel(const float* __restrict__ primary,
                   const float* __restrict__ vals,
                   float* __restrict__ out)
{
    __shared__ ull attn2[NSL*16];   // [n][row-pair], 12.8KB
    __shared__ float sg[32];
    __shared__ unsigned s_tile;
    int t = threadIdx.x;

    for (;;) {
        __syncthreads();             // previous tile's attn2 reads done
        if (t == 0) s_tile = atomicAdd(&g_out_ticket, 1u);
        __syncthreads();
        unsigned tile = s_tile;
        if (tile >= NOTILE) break;

        int row0 = (int)(tile >> 3) * 32;
        int c    = (int)(tile & 7) * 512 + t;

        if (t < 32) sg[t] = g_gate[row0 + t];
        __syncthreads();
        for (int idx = t; idx < NSL*16; idx += 512) {
            int n = idx >> 4, rp = idx & 15;
            float a0 = g_attn[(size_t)(row0 + 2*rp  )*NP + n];
            float a1 = g_attn[(size_t)(row0 + 2*rp+1)*NP + n];
            attn2[n*16 + rp] = pk2(a0*sg[2*rp], a1*sg[2*rp+1]);
        }
        __syncthreads();

        ull acc[16];
        #pragma unroll
        for (int rp = 0; rp < 16; ++rp) {
            size_t rb = (size_t)(row0 + rp*2) * HH;
            acc[rp] = pk2(primary[rb + c], primary[rb + HH + c]);
        }

        // 4-deep prefetch ring on vals (L2-resident)
        float vr[4];
        #pragma unroll
        for (int i = 0; i < 4; ++i) vr[i] = vals[(size_t)i*HH + c];

        #pragma unroll 4
        for (int n = 0; n < NSL; ++n) {
            int np = (n + 4 < NSL) ? n + 4 : NSL-1;
            float nv = vals[(size_t)np*HH + c];
            int sl = n & 3;                      // constant after unroll
            ull vv = pk2(vr[sl], vr[sl]);
            const float4* arow = (const float4*)(attn2 + n*16);
            #pragma unroll
            for (int j = 0; j < 8; ++j) {
                F4U u; u.f = arow[j];        // broadcast LDS.128
                fma2(acc[2*j],   u.u[0], vv);
                fma2(acc[2*j+1], u.u[1], vv);
            }
            vr[sl] = nv;
        }

        #pragma unroll
        for (int rp = 0; rp < 16; ++rp) {
            float x, y;
            size_t rb = (size_t)(row0 + rp*2) * HH;
            upk2(acc[rp], x, y);
            out[rb + c] = x;
            out[rb + HH + c] = y;
        }
    }
}

// ============================================================
extern "C" void kernel_launch(void* const* d_in, const int* in_sizes, int n_in,
                              void* d_out, int out_size)
{
    const float* hidden  = (const float*)d_in[0];  // [B,S,H]
    const float* primary = (const float*)d_in[1];  // [B,S,H]
    const float* paw     = (const float*)d_in[2];  // [B,NH,S,S]
    const float* rel     = (const float*)d_in[3];  // [NS]
    const float* Wq      = (const float*)d_in[4];  // [D,H]
    const float* keys    = (const float*)d_in[5];  // [NS,D]
    const float* vals    = (const float*)d_in[6];  // [NS,H]
    const float* gw1     = (const float*)d_in[7];  // scalar
    const float* gb      = (const float*)d_in[8];  // scalar
    float* out = (float*)d_out;

    cudaFuncSetAttribute(mega_kernel,
                         cudaFuncAttributeMaxDynamicSharedMemorySize,
                         SCORES_SMEM * (int)sizeof(float));

    reset_kernel<<<1, 32>>>();
    prep_kw<<<dim3(HH/256, 8), 256>>>(Wq, keys, rel);
    mega_kernel<<<NGRID, 256, SCORES_SMEM * sizeof(float)>>>(hidden, paw, gw1, gb);
    output_kernel<<<NOGRID, 512>>>(primary, vals, out);
}

// round 15
// speedup vs baseline: 1.2147x; 1.0002x over previous
#include <cuda_runtime.h>

// Problem shapes (fixed per reference setup_inputs)
#define BB  2
#define SS  2048
#define HH  4096
#define NHD 32
#define NSL 100
#define NP  128          // slots padded to 128
#define DD  64
#define BSR (BB*SS)      // 4096 rows

typedef unsigned long long ull;

// -------- scratch (no allocations allowed) --------
__device__ float g_gate[BSR];
__device__ float g_KW[HH*NP];       // (W_q^T keys^T)[h][n], pad n>=100 with 0
__device__ float g_logrelp[NP];     // log(rel+eps), pad = -1e30
__device__ float g_attn[BSR*NP];    // softmax(scores), un-gated
__device__ unsigned g_row_ticket;   // now counts ROW PAIRS (0..2047)
__device__ unsigned g_out_ticket;

// -------- packed f32x2 helpers --------
__device__ __forceinline__ ull pk2(float lo, float hi){
    ull r; asm("mov.b64 %0, {%1, %2};" : "=l"(r) : "f"(lo), "f"(hi)); return r;
}
__device__ __forceinline__ void upk2(ull v, float& lo, float& hi){
    asm("mov.b64 {%0, %1}, %2;" : "=f"(lo), "=f"(hi) : "l"(v));
}
__device__ __forceinline__ void fma2(ull& d, ull a, ull b){
    asm("fma.rn.f32x2 %0, %1, %2, %0;" : "+l"(d) : "l"(a), "l"(b));
}
union F4U { float4 f; ull u[2]; };

// ============================================================
// reset: tickets only
// ============================================================
__global__ void reset_kernel()
{
    if (threadIdx.x == 0) { g_row_ticket = 0u; g_out_ticket = 0u; }
}

// dummy: shifts the ncu capture slot so mega lands at position 3
__global__ void pad_kernel() {}

// ============================================================
// prep_kw: KW[h][n] = sum_d Wq[d][h]*keys[n][d]
// grid (16, 8): block y owns n in [16y, 16y+16) -> 128 CTAs
// ============================================================
__global__ __launch_bounds__(256)
void prep_kw(const float* __restrict__ Wq,
             const float* __restrict__ keys,
             const float* __restrict__ rel)
{
    __shared__ float sk[16*DD];
    int t = threadIdx.x;
    int n0 = blockIdx.y * 16;
    for (int i = t; i < 16*DD; i += 256) {
        int n = i >> 6, d = i & 63;
        sk[i] = ((n0 + n) < NSL) ? keys[(n0+n)*DD + d] : 0.f;
    }
    __syncthreads();

    int h = blockIdx.x*256 + t;
    float wv[DD];
    #pragma unroll
    for (int d = 0; d < DD; ++d) wv[d] = Wq[(size_t)d*HH + h];

    #pragma unroll 4
    for (int n = 0; n < 16; ++n) {
        float acc = 0.f;
        const float* kn = sk + n*DD;
        #pragma unroll
        for (int d = 0; d < DD; ++d) acc += wv[d]*kn[d];
        g_KW[(size_t)h*NP + n0 + n] = acc;
    }
    if (blockIdx.x == 0 && blockIdx.y == 0 && t < NP)
        g_logrelp[t] = (t < NSL) ? __logf(rel[t] + 1e-10f) : -1e30f;
}

// ============================================================
// mega: grid = 296 (2 CTAs/SM).  (R12 structure)
//   blocks [0,148)    : entropy ticket loop from t=0
//   blocks [148,276)  : one scores tile, then join entropy
//   blocks [276,296)  : entropy
// Entropy now processes 2 ADJACENT rows per ticket: halves
// barrier/ticket/epilogue overhead, 2 DRAM streams per CTA.
// ============================================================
#define NENT  148
#define NSCORE 128
#define NGRID (NENT + NSCORE + 20)   // 296

#define SKC 64
#define NCH (HH/SKC)     // 64 chunks
#define SCORES_SMEM (32*SKC*2 + SKC*NP)   // floats: 12288 -> 49152B

__device__ __forceinline__ void entropy_loop(const float* __restrict__ paw,
                                             float w1, float bb,
                                             unsigned* s_work, float* red)
{
    int t = threadIdx.x;
    for (;;) {
        __syncthreads();
        if (t == 0) *s_work = atomicAdd(&g_row_ticket, 1u);
        __syncthreads();
        unsigned pair = *s_work;
        if (pair >= BSR/2) break;
        unsigned rowA = pair*2;               // rowB = rowA+1, same batch

        size_t b = (size_t)(rowA >> 11);
        size_t s = (size_t)(rowA & 2047);
        const float* baseA = paw + ((b*NHD)*SS + s) * (size_t)SS;
        const float* baseB = baseA + SS;      // s+1 (s is even, stays in-batch)

        float4 a0 = make_float4(0.f,0.f,0.f,0.f);
        float4 a1 = make_float4(0.f,0.f,0.f,0.f);
        float4 c0 = make_float4(0.f,0.f,0.f,0.f);
        float4 c1 = make_float4(0.f,0.f,0.f,0.f);
        for (int h0 = 0; h0 < NHD; h0 += 4) {
            float4 xa0[4], xa1[4], xb0[4], xb1[4];
            #pragma unroll
            for (int u = 0; u < 4; ++u) {
                const float4* pA = (const float4*)(baseA + (size_t)(h0+u)*SS*SS);
                const float4* pB = (const float4*)(baseB + (size_t)(h0+u)*SS*SS);
                xa0[u] = pA[t];
                xa1[u] = pA[t + 256];
                xb0[u] = pB[t];
                xb1[u] = pB[t + 256];
            }
            #pragma unroll
            for (int u = 0; u < 4; ++u) {
                a0.x += xa0[u].x; a0.y += xa0[u].y; a0.z += xa0[u].z; a0.w += xa0[u].w;
                a1.x += xa1[u].x; a1.y += xa1[u].y; a1.z += xa1[u].z; a1.w += xa1[u].w;
                c0.x += xb0[u].x; c0.y += xb0[u].y; c0.z += xb0[u].z; c0.w += xb0[u].w;
                c1.x += xb1[u].x; c1.y += xb1[u].y; c1.z += xb1[u].z; c1.w += xb1[u].w;
            }
        }
        const float inv = 1.0f / 32.0f;
        float vA[8] = {a0.x,a0.y,a0.z,a0.w,a1.x,a1.y,a1.z,a1.w};
        float vB[8] = {c0.x,c0.y,c0.z,c0.w,c1.x,c1.y,c1.z,c1.w};
        float locA = 0.f, locB = 0.f;
        #pragma unroll
        for (int i = 0; i < 8; ++i) {
            float aa = vA[i] * inv;
            float ab = vB[i] * inv;
            locA += aa * __logf(aa + 1e-10f);
            locB += ab * __logf(ab + 1e-10f);
        }
        #pragma unroll
        for (int o = 16; o; o >>= 1) {
            locA += __shfl_xor_sync(0xffffffffu, locA, o);
            locB += __shfl_xor_sync(0xffffffffu, locB, o);
        }
        if ((t & 31) == 0) { red[(t>>5)*2] = locA; red[(t>>5)*2+1] = locB; }
        __syncthreads();
        if (t == 0) {
            float totA = 0.f, totB = 0.f;
            #pragma unroll
            for (int i = 0; i < 8; ++i) { totA += red[i*2]; totB += red[i*2+1]; }
            float eA = -totA, eB = -totB;
            float gA = 1.0f / (1.0f + __expf(-(w1*eA + bb)));
            float gB = 1.0f / (1.0f + __expf(-(w1*eB + bb)));
            if (eA < 0.5f)       gA = 0.f;
            else if (eA > 2.0f)  gA = fminf(gA, 0.8f);
            if (eB < 0.5f)       gB = 0.f;
            else if (eB > 2.0f)  gB = fminf(gB, 0.8f);
            g_gate[rowA]   = gA;
            g_gate[rowA+1] = gB;
        }
    }
}

__global__ __launch_bounds__(256, 2)
void mega_kernel(const float* __restrict__ hidden,
                 const float* __restrict__ paw,
                 const float* __restrict__ w1p,
                 const float* __restrict__ bp)
{
    extern __shared__ float smraw[];
    __shared__ float red[16];
    __shared__ unsigned s_work;
    int t = threadIdx.x;
    int bid = blockIdx.x;

    if (bid >= NENT && bid < NENT + NSCORE) {
        // =================== one scores tile ===================
        float2* sh = (float2*)smraw;             // [32][SKC] dup pairs, 16KB
        float*  sw = smraw + 32*SKC*2;           // [SKC][NP], 32KB
        int w = t>>5, lane = t&31;
        int row0 = (bid - NENT)*32;

        float4 ph[2], pw[8];
        #pragma unroll
        for (int i = 0; i < 2; ++i) {
            int idx = t + i*256, rr = idx>>4, c4 = idx&15;
            ph[i] = *(const float4*)(hidden + (size_t)(row0+rr)*HH + (c4<<2));
        }
        #pragma unroll
        for (int i = 0; i < 8; ++i) {
            int idx = t + i*256, kk = idx>>5, c4 = idx&31;
            pw[i] = *(const float4*)(g_KW + (size_t)kk*NP + (c4<<2));
        }

        ull a[4][2] = {{0,0},{0,0},{0,0},{0,0}};

        for (int c = 0; c < NCH; ++c) {
            __syncthreads();
            #pragma unroll
            for (int i = 0; i < 2; ++i) {
                int idx = t + i*256, rr = idx>>4, c4 = idx&15;
                float2* d = &sh[rr*SKC + (c4<<2)];
                d[0] = make_float2(ph[i].x, ph[i].x);
                d[1] = make_float2(ph[i].y, ph[i].y);
                d[2] = make_float2(ph[i].z, ph[i].z);
                d[3] = make_float2(ph[i].w, ph[i].w);
            }
            #pragma unroll
            for (int i = 0; i < 8; ++i) {
                int idx = t + i*256, kk = idx>>5, c4 = idx&31;
                *(float4*)(sw + kk*NP + (c4<<2)) = pw[i];
            }
            __syncthreads();

            if (c + 1 < NCH) {
                int k0 = (c+1)*SKC;
                #pragma unroll
                for (int i = 0; i < 2; ++i) {
                    int idx = t + i*256, rr = idx>>4, c4 = idx&15;
                    ph[i] = *(const float4*)(hidden + (size_t)(row0+rr)*HH + k0 + (c4<<2));
                }
                #pragma unroll
                for (int i = 0; i < 8; ++i) {
                    int idx = t + i*256, kk = idx>>5, c4 = idx&31;
                    pw[i] = *(const float4*)(g_KW + (size_t)(k0+kk)*NP + (c4<<2));
                }
            }

            const ull* h0 = (const ull*)&sh[(w*4+0)*SKC];
            const ull* h1 = (const ull*)&sh[(w*4+1)*SKC];
            const ull* h2 = (const ull*)&sh[(w*4+2)*SKC];
            const ull* h3 = (const ull*)&sh[(w*4+3)*SKC];
            #pragma unroll 8
            for (int k = 0; k < SKC; ++k) {
                F4U kw; kw.f = *(const float4*)(sw + k*NP + (lane<<2));
                ull hh0 = h0[k], hh1 = h1[k], hh2 = h2[k], hh3 = h3[k];
                fma2(a[0][0], kw.u[0], hh0); fma2(a[0][1], kw.u[1], hh0);
                fma2(a[1][0], kw.u[0], hh1); fma2(a[1][1], kw.u[1], hh1);
                fma2(a[2][0], kw.u[0], hh2); fma2(a[2][1], kw.u[1], hh2);
                fma2(a[3][0], kw.u[0], hh3); fma2(a[3][1], kw.u[1], hh3);
            }
        }

        // softmax per row (pad n>=100 has logrel=-1e30 -> exp=0)
        float4 lr = *(const float4*)(g_logrelp + (lane<<2));
        #pragma unroll
        for (int j = 0; j < 4; ++j) {
            int row = row0 + w*4 + j;
            float s0,s1,s2,s3;
            upk2(a[j][0], s0, s1); upk2(a[j][1], s2, s3);
            s0 = 0.125f*s0 + lr.x; s1 = 0.125f*s1 + lr.y;
            s2 = 0.125f*s2 + lr.z; s3 = 0.125f*s3 + lr.w;
            float m = fmaxf(fmaxf(s0,s1), fmaxf(s2,s3));
            #pragma unroll
            for (int o = 16; o; o >>= 1) m = fmaxf(m, __shfl_xor_sync(0xffffffffu, m, o));
            float e0 = __expf(s0-m), e1 = __expf(s1-m);
            float e2 = __expf(s2-m), e3 = __expf(s3-m);
            float sum = e0+e1+e2+e3;
            #pragma unroll
            for (int o = 16; o; o >>= 1) sum += __shfl_xor_sync(0xffffffffu, sum, o);
            float invs = 1.0f / sum;
            float4 o4 = make_float4(e0*invs, e1*invs, e2*invs, e3*invs);
            *(float4*)(g_attn + (size_t)row*NP + (lane<<2)) = o4;
        }
    }

    // =================== entropy (all CTAs) ===================
    entropy_loop(paw, w1p[0], bp[0], &s_work, red);
}

// ============================================================
// output: out = primary + gate[row]*(attn @ vals)
// PERSISTENT: grid 296 x 512 thr, ticket loop over 1024 tiles.
// vals ring deepened to 8 (prefetch distance ~= L2 latency);
// main loop unroll-8 over n<96 + 4-tail keeps slots constant.
// ============================================================
#define NOTILE (BSR/32 * 8)   // 1024 tiles
#define NOGRID 296

__global__ __launch_bounds__(512, 2)
void output_kernel(const float* __restrict__ primary,
                   const float* __restrict__ vals,
                   float* __restrict__ out)
{
    __shared__ ull attn2[NSL*16];   // [n][row-pair], 12.8KB
    __shared__ float sg[32];
    __shared__ unsigned s_tile;
    int t = threadIdx.x;

    for (;;) {
        __syncthreads();             // previous tile's attn2 reads done
        if (t == 0) s_tile = atomicAdd(&g_out_ticket, 1u);
        __syncthreads();
        unsigned tile = s_tile;
        if (tile >= NOTILE) break;

        int row0 = (int)(tile >> 3) * 32;
        int c    = (int)(tile & 7) * 512 + t;

        if (t < 32) sg[t] = g_gate[row0 + t];
        __syncthreads();
        for (int idx = t; idx < NSL*16; idx += 512) {
            int n = idx >> 4, rp = idx & 15;
            float a0 = g_attn[(size_t)(row0 + 2*rp  )*NP + n];
            float a1 = g_attn[(size_t)(row0 + 2*rp+1)*NP + n];
            attn2[n*16 + rp] = pk2(a0*sg[2*rp], a1*sg[2*rp+1]);
        }
        __syncthreads();

        ull acc[16];
        #pragma unroll
        for (int rp = 0; rp < 16; ++rp) {
            size_t rb = (size_t)(row0 + rp*2) * HH;
            acc[rp] = pk2(primary[rb + c], primary[rb + HH + c]);
        }

        // 8-deep prefetch ring on vals (covers L2 latency)
        float vr[8];
        #pragma unroll
        for (int i = 0; i < 8; ++i) vr[i] = vals[(size_t)i*HH + c];

        for (int n = 0; n < 96; n += 8) {
            #pragma unroll
            for (int u = 0; u < 8; ++u) {
                int nn = n + u;
                int np = (nn + 8 < NSL) ? nn + 8 : NSL-1;
                float nv = vals[(size_t)np*HH + c];
                ull vv = pk2(vr[u], vr[u]);
                const float4* arow = (const float4*)(attn2 + nn*16);
                #pragma unroll
                for (int j = 0; j < 8; ++j) {
                    F4U x; x.f = arow[j];        // broadcast LDS.128
                    fma2(acc[2*j],   x.u[0], vv);
                    fma2(acc[2*j+1], x.u[1], vv);
                }
                vr[u] = nv;
            }
        }
        // tail n = 96..99 (values sit in vr[0..3] after last main iter)
        #pragma unroll
        for (int u = 0; u < 4; ++u) {
            int nn = 96 + u;
            ull vv = pk2(vr[u], vr[u]);
            const float4* arow = (const float4*)(attn2 + nn*16);
            #pragma unroll
            for (int j = 0; j < 8; ++j) {
                F4U x; x.f = arow[j];
                fma2(acc[2*j],   x.u[0], vv);
                fma2(acc[2*j+1], x.u[1], vv);
            }
        }

        #pragma unroll
        for (int rp = 0; rp < 16; ++rp) {
            float x, y;
            size_t rb = (size_t)(row0 + rp*2) * HH;
            upk2(acc[rp], x, y);
            out[rb + c] = x;
            out[rb + HH + c] = y;
        }
    }
}

// ============================================================
extern "C" void kernel_launch(void* const* d_in, const int* in_sizes, int n_in,
                              void* d_out, int out_size)
{
    const float* hidden  = (const float*)d_in[0];  // [B,S,H]
    const float* primary = (const float*)d_in[1];  // [B,S,H]
    const float* paw     = (const float*)d_in[2];  // [B,NH,S,S]
    const float* rel     = (const float*)d_in[3];  // [NS]
    const float* Wq      = (const float*)d_in[4];  // [D,H]
    const float* keys    = (const float*)d_in[5];  // [NS,D]
    const float* vals    = (const float*)d_in[6];  // [NS,H]
    const float* gw1     = (const float*)d_in[7];  // scalar
    const float* gb      = (const float*)d_in[8];  // scalar
    float* out = (float*)d_out;

    cudaFuncSetAttribute(mega_kernel,
                         cudaFuncAttributeMaxDynamicSharedMemorySize,
                         SCORES_SMEM * (int)sizeof(float));

    reset_kernel<<<1, 32>>>();                     // pos 0
    prep_kw<<<dim3(HH/256, 8), 256>>>(Wq, keys, rel);  // pos 1
    pad_kernel<<<1, 32>>>();                       // pos 2 (ncu slot shim)
    mega_kernel<<<NGRID, 256, SCORES_SMEM * sizeof(float)>>>(hidden, paw, gw1, gb); // pos 3
    output_kernel<<<NOGRID, 512>>>(primary, vals, out); // pos 4
}

// round 16
// speedup vs baseline: 1.2224x; 1.0064x over previous
#include <cuda_runtime.h>

// Problem shapes (fixed per reference setup_inputs)
#define BB  2
#define SS  2048
#define HH  4096
#define NHD 32
#define NSL 100
#define NP  128          // slots padded to 128
#define DD  64
#define BSR (BB*SS)      // 4096 rows

typedef unsigned long long ull;

// -------- scratch (no allocations allowed) --------
__device__ float g_gate[BSR];
__device__ float g_KW[HH*NP];       // (W_q^T keys^T)[h][n], pad n>=100 with 0
__device__ float g_logrelp[NP];     // log(rel+eps), pad = -1e30
__device__ float g_attn[BSR*NP];    // softmax(scores), un-gated
__device__ unsigned g_row_ticket;
__device__ unsigned g_out_ticket;

// -------- packed f32x2 helpers --------
__device__ __forceinline__ ull pk2(float lo, float hi){
    ull r; asm("mov.b64 %0, {%1, %2};" : "=l"(r) : "f"(lo), "f"(hi)); return r;
}
__device__ __forceinline__ void upk2(ull v, float& lo, float& hi){
    asm("mov.b64 {%0, %1}, %2;" : "=f"(lo), "=f"(hi) : "l"(v));
}
__device__ __forceinline__ void fma2(ull& d, ull a, ull b){
    asm("fma.rn.f32x2 %0, %1, %2, %0;" : "+l"(d) : "l"(a), "l"(b));
}
union F4U { float4 f; ull u[2]; };

// ============================================================
// prep_kw: KW[h][n] = sum_d Wq[d][h]*keys[n][d]; logrelp;
// ticket reset (runs first -> stream-ordered before consumers)
// grid (16, 8): block y owns n in [16y, 16y+16) -> 128 CTAs
// ============================================================
__global__ __launch_bounds__(256)
void prep_kw(const float* __restrict__ Wq,
             const float* __restrict__ keys,
             const float* __restrict__ rel)
{
    __shared__ float sk[16*DD];
    int t = threadIdx.x;
    int n0 = blockIdx.y * 16;
    for (int i = t; i < 16*DD; i += 256) {
        int n = i >> 6, d = i & 63;
        sk[i] = ((n0 + n) < NSL) ? keys[(n0+n)*DD + d] : 0.f;
    }
    __syncthreads();

    int h = blockIdx.x*256 + t;
    float wv[DD];
    #pragma unroll
    for (int d = 0; d < DD; ++d) wv[d] = Wq[(size_t)d*HH + h];

    #pragma unroll 4
    for (int n = 0; n < 16; ++n) {
        float acc = 0.f;
        const float* kn = sk + n*DD;
        #pragma unroll
        for (int d = 0; d < DD; ++d) acc += wv[d]*kn[d];
        g_KW[(size_t)h*NP + n0 + n] = acc;
    }
    if (blockIdx.x == 0 && blockIdx.y == 0 && t < NP)
        g_logrelp[t] = (t < NSL) ? __logf(rel[t] + 1e-10f) : -1e30f;
    if (blockIdx.x == 0 && blockIdx.y == 0 && t == 0) {
        g_row_ticket = 0u;
        g_out_ticket = 0u;
    }
}

// ============================================================
// mega: grid = 296 (2 CTAs/SM).  (exact R12 structure)
//   blocks [0,148)    : entropy ticket loop from t=0
//   blocks [148,276)  : one scores tile, then join entropy
//   blocks [276,296)  : entropy
// ============================================================
#define NENT  148
#define NSCORE 128
#define NGRID (NENT + NSCORE + 20)   // 296

#define SKC 64
#define NCH (HH/SKC)     // 64 chunks
#define SCORES_SMEM (32*SKC*2 + SKC*NP)   // floats: 12288 -> 49152B

__device__ __forceinline__ void entropy_loop(const float* __restrict__ paw,
                                             float w1, float bb,
                                             unsigned* s_work, float* red)
{
    int t = threadIdx.x;
    for (;;) {
        __syncthreads();
        if (t == 0) *s_work = atomicAdd(&g_row_ticket, 1u);
        __syncthreads();
        unsigned row = *s_work;
        if (row >= BSR) break;

        size_t b = (size_t)(row >> 11);
        size_t s = (size_t)(row & 2047);
        const float* base = paw + ((b*NHD)*SS + s) * (size_t)SS;

        float4 a0 = make_float4(0.f,0.f,0.f,0.f);
        float4 a1 = make_float4(0.f,0.f,0.f,0.f);
        for (int h0 = 0; h0 < NHD; h0 += 8) {
            float4 x0[8], x1[8];
            #pragma unroll
            for (int u = 0; u < 8; ++u) {
                const float4* p = (const float4*)(base + (size_t)(h0+u)*SS*SS);
                x0[u] = p[t];
                x1[u] = p[t + 256];
            }
            #pragma unroll
            for (int u = 0; u < 8; ++u) {
                a0.x += x0[u].x; a0.y += x0[u].y; a0.z += x0[u].z; a0.w += x0[u].w;
                a1.x += x1[u].x; a1.y += x1[u].y; a1.z += x1[u].z; a1.w += x1[u].w;
            }
        }
        const float inv = 1.0f / 32.0f;
        float v[8] = {a0.x,a0.y,a0.z,a0.w,a1.x,a1.y,a1.z,a1.w};
        float loc = 0.f;
        #pragma unroll
        for (int i = 0; i < 8; ++i) {
            float a = v[i] * inv;
            loc += a * __logf(a + 1e-10f);
        }
        #pragma unroll
        for (int o = 16; o; o >>= 1) loc += __shfl_xor_sync(0xffffffffu, loc, o);
        if ((t & 31) == 0) red[t >> 5] = loc;
        __syncthreads();
        if (t == 0) {
            float tot = 0.f;
            #pragma unroll
            for (int i = 0; i < 8; ++i) tot += red[i];
            float e = -tot;
            float g = 1.0f / (1.0f + __expf(-(w1*e + bb)));
            if (e < 0.5f)       g = 0.f;
            else if (e > 2.0f)  g = fminf(g, 0.8f);
            g_gate[row] = g;
        }
    }
}

__global__ __launch_bounds__(256, 2)
void mega_kernel(const float* __restrict__ hidden,
                 const float* __restrict__ paw,
                 const float* __restrict__ w1p,
                 const float* __restrict__ bp)
{
    extern __shared__ float smraw[];
    __shared__ float red[8];
    __shared__ unsigned s_work;
    int t = threadIdx.x;
    int bid = blockIdx.x;

    if (bid >= NENT && bid < NENT + NSCORE) {
        // =================== one scores tile ===================
        float2* sh = (float2*)smraw;             // [32][SKC] dup pairs, 16KB
        float*  sw = smraw + 32*SKC*2;           // [SKC][NP], 32KB
        int w = t>>5, lane = t&31;
        int row0 = (bid - NENT)*32;

        float4 ph[2], pw[8];
        #pragma unroll
        for (int i = 0; i < 2; ++i) {
            int idx = t + i*256, rr = idx>>4, c4 = idx&15;
            ph[i] = *(const float4*)(hidden + (size_t)(row0+rr)*HH + (c4<<2));
        }
        #pragma unroll
        for (int i = 0; i < 8; ++i) {
            int idx = t + i*256, kk = idx>>5, c4 = idx&31;
            pw[i] = *(const float4*)(g_KW + (size_t)kk*NP + (c4<<2));
        }

        ull a[4][2] = {{0,0},{0,0},{0,0},{0,0}};

        for (int c = 0; c < NCH; ++c) {
            __syncthreads();
            #pragma unroll
            for (int i = 0; i < 2; ++i) {
                int idx = t + i*256, rr = idx>>4, c4 = idx&15;
                float2* d = &sh[rr*SKC + (c4<<2)];
                d[0] = make_float2(ph[i].x, ph[i].x);
                d[1] = make_float2(ph[i].y, ph[i].y);
                d[2] = make_float2(ph[i].z, ph[i].z);
                d[3] = make_float2(ph[i].w, ph[i].w);
            }
            #pragma unroll
            for (int i = 0; i < 8; ++i) {
                int idx = t + i*256, kk = idx>>5, c4 = idx&31;
                *(float4*)(sw + kk*NP + (c4<<2)) = pw[i];
            }
            __syncthreads();

            if (c + 1 < NCH) {
                int k0 = (c+1)*SKC;
                #pragma unroll
                for (int i = 0; i < 2; ++i) {
                    int idx = t + i*256, rr = idx>>4, c4 = idx&15;
                    ph[i] = *(const float4*)(hidden + (size_t)(row0+rr)*HH + k0 + (c4<<2));
                }
                #pragma unroll
                for (int i = 0; i < 8; ++i) {
                    int idx = t + i*256, kk = idx>>5, c4 = idx&31;
                    pw[i] = *(const float4*)(g_KW + (size_t)(k0+kk)*NP + (c4<<2));
                }
            }

            const ull* h0 = (const ull*)&sh[(w*4+0)*SKC];
            const ull* h1 = (const ull*)&sh[(w*4+1)*SKC];
            const ull* h2 = (const ull*)&sh[(w*4+2)*SKC];
            const ull* h3 = (const ull*)&sh[(w*4+3)*SKC];
            #pragma unroll 8
            for (int k = 0; k < SKC; ++k) {
                F4U kw; kw.f = *(const float4*)(sw + k*NP + (lane<<2));
                ull hh0 = h0[k], hh1 = h1[k], hh2 = h2[k], hh3 = h3[k];
                fma2(a[0][0], kw.u[0], hh0); fma2(a[0][1], kw.u[1], hh0);
                fma2(a[1][0], kw.u[0], hh1); fma2(a[1][1], kw.u[1], hh1);
                fma2(a[2][0], kw.u[0], hh2); fma2(a[2][1], kw.u[1], hh2);
                fma2(a[3][0], kw.u[0], hh3); fma2(a[3][1], kw.u[1], hh3);
            }
        }

        // softmax per row (pad n>=100 has logrel=-1e30 -> exp=0)
        float4 lr = *(const float4*)(g_logrelp + (lane<<2));
        #pragma unroll
        for (int j = 0; j < 4; ++j) {
            int row = row0 + w*4 + j;
            float s0,s1,s2,s3;
            upk2(a[j][0], s0, s1); upk2(a[j][1], s2, s3);
            s0 = 0.125f*s0 + lr.x; s1 = 0.125f*s1 + lr.y;
            s2 = 0.125f*s2 + lr.z; s3 = 0.125f*s3 + lr.w;
            float m = fmaxf(fmaxf(s0,s1), fmaxf(s2,s3));
            #pragma unroll
            for (int o = 16; o; o >>= 1) m = fmaxf(m, __shfl_xor_sync(0xffffffffu, m, o));
            float e0 = __expf(s0-m), e1 = __expf(s1-m);
            float e2 = __expf(s2-m), e3 = __expf(s3-m);
            float sum = e0+e1+e2+e3;
            #pragma unroll
            for (int o = 16; o; o >>= 1) sum += __shfl_xor_sync(0xffffffffu, sum, o);
            float invs = 1.0f / sum;
            float4 o4 = make_float4(e0*invs, e1*invs, e2*invs, e3*invs);
            *(float4*)(g_attn + (size_t)row*NP + (lane<<2)) = o4;
        }
    }

    // =================== entropy (all CTAs) ===================
    entropy_loop(paw, w1p[0], bp[0], &s_work, red);
}

// ============================================================
// output: out = primary + gate[row]*(attn @ vals)
// PERSISTENT: grid 296 x 512 thr, ticket loop over 1024 tiles.
// 8-deep vals ring (covers L2 latency); unroll-8 + 4-tail keeps
// ring slots compile-time constant (no local-memory spill).
// ============================================================
#define NOTILE (BSR/32 * 8)   // 1024 tiles
#define NOGRID 296

__global__ __launch_bounds__(512, 2)
void output_kernel(const float* __restrict__ primary,
                   const float* __restrict__ vals,
                   float* __restrict__ out)
{
    __shared__ ull attn2[NSL*16];   // [n][row-pair], 12.8KB
    __shared__ float sg[32];
    __shared__ unsigned s_tile;
    int t = threadIdx.x;

    for (;;) {
        __syncthreads();             // previous tile's attn2 reads done
        if (t == 0) s_tile = atomicAdd(&g_out_ticket, 1u);
        __syncthreads();
        unsigned tile = s_tile;
        if (tile >= NOTILE) break;

        int row0 = (int)(tile >> 3) * 32;
        int c    = (int)(tile & 7) * 512 + t;

        if (t < 32) sg[t] = g_gate[row0 + t];
        __syncthreads();
        for (int idx = t; idx < NSL*16; idx += 512) {
            int n = idx >> 4, rp = idx & 15;
            float a0 = g_attn[(size_t)(row0 + 2*rp  )*NP + n];
            float a1 = g_attn[(size_t)(row0 + 2*rp+1)*NP + n];
            attn2[n*16 + rp] = pk2(a0*sg[2*rp], a1*sg[2*rp+1]);
        }
        __syncthreads();

        ull acc[16];
        #pragma unroll
        for (int rp = 0; rp < 16; ++rp) {
            size_t rb = (size_t)(row0 + rp*2) * HH;
            acc[rp] = pk2(primary[rb + c], primary[rb + HH + c]);
        }

        // 8-deep prefetch ring on vals (covers L2 latency)
        float vr[8];
        #pragma unroll
        for (int i = 0; i < 8; ++i) vr[i] = vals[(size_t)i*HH + c];

        for (int n = 0; n < 96; n += 8) {
            #pragma unroll
            for (int u = 0; u < 8; ++u) {
                int nn = n + u;
                int np = (nn + 8 < NSL) ? nn + 8 : NSL-1;
                float nv = vals[(size_t)np*HH + c];
                ull vv = pk2(vr[u], vr[u]);
                const float4* arow = (const float4*)(attn2 + nn*16);
                #pragma unroll
                for (int j = 0; j < 8; ++j) {
                    F4U x; x.f = arow[j];        // broadcast LDS.128
                    fma2(acc[2*j],   x.u[0], vv);
                    fma2(acc[2*j+1], x.u[1], vv);
                }
                vr[u] = nv;
            }
        }
        // tail n = 96..99 (values sit in vr[0..3] after last main iter)
        #pragma unroll
        for (int u = 0; u < 4; ++u) {
            int nn = 96 + u;
            ull vv = pk2(vr[u], vr[u]);
            const float4* arow = (const float4*)(attn2 + nn*16);
            #pragma unroll
            for (int j = 0; j < 8; ++j) {
                F4U x; x.f = arow[j];
                fma2(acc[2*j],   x.u[0], vv);
                fma2(acc[2*j+1], x.u[1], vv);
            }
        }

        #pragma unroll
        for (int rp = 0; rp < 16; ++rp) {
            float x, y;
            size_t rb = (size_t)(row0 + rp*2) * HH;
            upk2(acc[rp], x, y);
            out[rb + c] = x;
            out[rb + HH + c] = y;
        }
    }
}

// ============================================================
extern "C" void kernel_launch(void* const* d_in, const int* in_sizes, int n_in,
                              void* d_out, int out_size)
{
    const float* hidden  = (const float*)d_in[0];  // [B,S,H]
    const float* primary = (const float*)d_in[1];  // [B,S,H]
    const float* paw     = (const float*)d_in[2];  // [B,NH,S,S]
    const float* rel     = (const float*)d_in[3];  // [NS]
    const float* Wq      = (const float*)d_in[4];  // [D,H]
    const float* keys    = (const float*)d_in[5];  // [NS,D]
    const float* vals    = (const float*)d_in[6];  // [NS,H]
    const float* gw1     = (const float*)d_in[7];  // scalar
    const float* gb      = (const float*)d_in[8];  // scalar
    float* out = (float*)d_out;

    cudaFuncSetAttribute(mega_kernel,
                         cudaFuncAttributeMaxDynamicSharedMemorySize,
                         SCORES_SMEM * (int)sizeof(float));

    prep_kw<<<dim3(HH/256, 8), 256>>>(Wq, keys, rel);
    mega_kernel<<<NGRID, 256, SCORES_SMEM * sizeof(float)>>>(hidden, paw, gw1, gb);
    output_kernel<<<NOGRID, 512>>>(primary, vals, out);
}